// round 2
// baseline (speedup 1.0000x reference)
#include <cuda_runtime.h>
#include <cuda_bf16.h>
#include <cstdint>

// ---------------------------------------------------------------------------
// Problem constants
// ---------------------------------------------------------------------------
#define BATCH 32
#define SDIM  65536      // H*W = 256*256
#define RANK  128
#define NDEG  4
#define BN_EPS 1e-5f

typedef unsigned long long ull;

// ---------------------------------------------------------------------------
// Scratch (device globals -- no allocations allowed)
// ---------------------------------------------------------------------------
#define NCHUNK 256                      // s-chunks per degree in the t-GEMM
__device__ float2 g_bn_partial[512];
__device__ float  g_scale[2];           // a, c : z = a*x + c
__device__ float  g_partial_t[NDEG][NCHUNK][BATCH][RANK];   // 16.8 MB
__device__ float  g_partial2[NDEG][8][BATCH][RANK];         // 512 KB
__device__ float  g_h[BATCH][RANK];

// ---------------------------------------------------------------------------
// f32x2 packed-FMA helpers (Blackwell sm_100a)
// ---------------------------------------------------------------------------
__device__ __forceinline__ ull pack2(float lo, float hi) {
    ull r;
    asm("mov.b64 %0, {%1, %2};" : "=l"(r)
        : "r"(__float_as_uint(lo)), "r"(__float_as_uint(hi)));
    return r;
}
__device__ __forceinline__ void unpack2(ull v, float& lo, float& hi) {
    unsigned ulo, uhi;
    asm("mov.b64 {%0, %1}, %2;" : "=r"(ulo), "=r"(uhi) : "l"(v));
    lo = __uint_as_float(ulo);
    hi = __uint_as_float(uhi);
}
__device__ __forceinline__ void ffma2(ull& d, ull a, ull b) {
    asm("fma.rn.f32x2 %0, %1, %2, %0;" : "+l"(d) : "l"(a), "l"(b));
}

// ---------------------------------------------------------------------------
// Kernel 1a: per-block partial sum / sumsq of x  (fixed contiguous partition)
// grid 512 x 256, each block owns 4096 contiguous elements
// ---------------------------------------------------------------------------
__global__ void __launch_bounds__(256) bn_partial_kernel(const float* __restrict__ x) {
    const int tid = threadIdx.x;
    const size_t base = (size_t)blockIdx.x * 4096;
    float s1 = 0.f, s2 = 0.f;
#pragma unroll
    for (int k = 0; k < 16; k++) {
        float v = x[base + (size_t)k * 256 + tid];
        s1 += v;
        s2 += v * v;
    }
    __shared__ float sh1[256], sh2[256];
    sh1[tid] = s1; sh2[tid] = s2;
    __syncthreads();
    for (int o = 128; o > 0; o >>= 1) {
        if (tid < o) { sh1[tid] += sh1[tid + o]; sh2[tid] += sh2[tid + o]; }
        __syncthreads();
    }
    if (tid == 0) g_bn_partial[blockIdx.x] = make_float2(sh1[0], sh2[0]);
}

// ---------------------------------------------------------------------------
// Kernel 1b: finalize BN -> affine scalars a, c
// ---------------------------------------------------------------------------
__global__ void __launch_bounds__(512) bn_finalize_kernel(const float* __restrict__ gamma,
                                                          const float* __restrict__ bnb) {
    const int tid = threadIdx.x;
    __shared__ float sh1[512], sh2[512];
    float2 p = g_bn_partial[tid];
    sh1[tid] = p.x; sh2[tid] = p.y;
    __syncthreads();
    for (int o = 256; o > 0; o >>= 1) {
        if (tid < o) { sh1[tid] += sh1[tid + o]; sh2[tid] += sh2[tid + o]; }
        __syncthreads();
    }
    if (tid == 0) {
        const float M = (float)((size_t)BATCH * SDIM);   // 2097152
        float mean = sh1[0] / M;
        float var  = sh2[0] / M - mean * mean;
        float rstd = rsqrtf(var + BN_EPS);
        float a = gamma[0] * rstd;
        g_scale[0] = a;
        g_scale[1] = bnb[0] - mean * a;
    }
}

// ---------------------------------------------------------------------------
// Kernel 2: partial t[n][b][r] = sum_{s in chunk} z[b][s] * U[n][s][r]
// grid (NCHUNK, NDEG) x 128 threads.
// Thread layout: lane_r = tid&31 -> r = 4*lane_r..+3 (float4 U loads,
// warp covers the full 512B U row, coalesced). bq = tid>>5 (== warp id)
// -> b = bq*8..+7 packed as 4 f32x2 b-pairs (broadcast LDS.64 from shared).
// acc[b2][rj] : 4x4 f32x2 = 32 MACs / thread / s.
// ---------------------------------------------------------------------------
#define SCHUNK (SDIM / NCHUNK)   // 256
#define TS 32

__global__ void __launch_bounds__(128) poly_t_kernel(const float* __restrict__ x,
                                                     const float* __restrict__ U) {
    const int n     = blockIdx.y;
    const int chunk = blockIdx.x;
    const int tid   = threadIdx.x;
    const int lane_r = (tid & 31);
    const int bq     = tid >> 5;             // 0..3
    const float a = g_scale[0];
    const float c = g_scale[1];

    __shared__ __align__(16) float zsh[TS][BATCH + 2];   // [s][b], row = 34 floats (8B-aligned pairs)

    ull acc[4][4];
#pragma unroll
    for (int i = 0; i < 4; i++)
#pragma unroll
        for (int j = 0; j < 4; j++) acc[i][j] = 0ull;

    const int s_base = chunk * SCHUNK;
    const float* Up = U + ((size_t)n * SDIM + s_base) * RANK + lane_r * 4;

    for (int st = 0; st < SCHUNK; st += TS) {
        __syncthreads();
        // stage z tile: TS x BATCH = 1024 floats, coalesced global reads
#pragma unroll
        for (int k = 0; k < (TS * BATCH) / 128; k++) {   // 8
            int idx = k * 128 + tid;
            int ss  = idx & (TS - 1);
            int bb  = idx >> 5;
            zsh[ss][bb] = a * x[(size_t)bb * SDIM + s_base + st + ss] + c;
        }
        __syncthreads();
#pragma unroll 4
        for (int s = 0; s < TS; s++) {
            const float4 u4 = *(const float4*)(Up + (size_t)(st + s) * RANK);
            ull uu0 = pack2(u4.x, u4.x);
            ull uu1 = pack2(u4.y, u4.y);
            ull uu2 = pack2(u4.z, u4.z);
            ull uu3 = pack2(u4.w, u4.w);
#pragma unroll
            for (int i = 0; i < 4; i++) {
                ull z2 = *(const ull*)&zsh[s][bq * 8 + 2 * i];   // broadcast within warp
                ffma2(acc[i][0], z2, uu0);
                ffma2(acc[i][1], z2, uu1);
                ffma2(acc[i][2], z2, uu2);
                ffma2(acc[i][3], z2, uu3);
            }
        }
    }

    // write per-block partials, coalesced float4 stores
    float* pt = &g_partial_t[n][chunk][0][0];
#pragma unroll
    for (int i = 0; i < 4; i++) {
        float v0[4], v1[4];
#pragma unroll
        for (int j = 0; j < 4; j++) unpack2(acc[i][j], v0[j], v1[j]);
        int b_lo = bq * 8 + 2 * i;
        *(float4*)&pt[(size_t)b_lo       * RANK + lane_r * 4] = make_float4(v0[0], v0[1], v0[2], v0[3]);
        *(float4*)&pt[(size_t)(b_lo + 1) * RANK + lane_r * 4] = make_float4(v1[0], v1[1], v1[2], v1[3]);
    }
}

// ---------------------------------------------------------------------------
// Kernel 3a: reduce 256 chunks -> 8 groups (fixed order, deterministic)
// grid 512 x 256 : idx -> (n, g, b, r), each sums 32 chunks
// ---------------------------------------------------------------------------
__global__ void __launch_bounds__(256) reduce_partial_kernel() {
    const int idx = blockIdx.x * 256 + threadIdx.x;   // 0..131071
    const int r = idx & 127;
    const int b = (idx >> 7) & 31;
    const int g = (idx >> 12) & 7;
    const int n = idx >> 15;
    const float* p = &g_partial_t[n][g * 32][b][r];
    float sum = 0.f;
#pragma unroll 8
    for (int cc = 0; cc < 32; cc++) sum += p[(size_t)cc * BATCH * RANK];
    g_partial2[n][g][b][r] = sum;
}

// ---------------------------------------------------------------------------
// Kernel 3b: final reduce + degree-4 CCP recursion -> h[b][r]
// grid 16 x 256 : idx -> (b, r)
// ---------------------------------------------------------------------------
__global__ void __launch_bounds__(256) finalize_h_kernel() {
    const int idx = blockIdx.x * 256 + threadIdx.x;   // 0..4095
    const int b = idx >> 7;
    const int r = idx & 127;
    float t[NDEG];
#pragma unroll
    for (int n = 0; n < NDEG; n++) {
        float s = 0.f;
#pragma unroll
        for (int g = 0; g < 8; g++) s += g_partial2[n][g][b][r];
        t[n] = s;
    }
    float h = t[0];
#pragma unroll
    for (int n = 1; n < NDEG; n++) h = t[n] * h + h;
    g_h[b][r] = h;
}

// ---------------------------------------------------------------------------
// Kernel 4: out[b][s] = beta[s] + sum_r h[b][r] * C[s][r]
// grid (SDIM/64) x 256. Thread owns one s (tid&63) and 8 b rows (tid>>6),
// h transposed in shared so b-pairs are broadcast LDS.64.
// ---------------------------------------------------------------------------
#define TILE_S4 64

__global__ void __launch_bounds__(256) out_kernel(const float* __restrict__ C,
                                                  const float* __restrict__ beta,
                                                  float* __restrict__ out) {
    __shared__ __align__(16) float hsh[RANK][BATCH + 2];   // [r][b]
    const int tid = threadIdx.x;
    for (int idx = tid; idx < BATCH * RANK; idx += 256) {
        int b = idx >> 7, r = idx & 127;
        hsh[r][b] = g_h[b][r];
    }
    __syncthreads();

    const int s  = blockIdx.x * TILE_S4 + (tid & 63);
    const int bg = tid >> 6;                 // 0..3 -> b = bg*8..+7

    ull acc[4];
#pragma unroll
    for (int i = 0; i < 4; i++) acc[i] = 0ull;

    const float* Cp = C + (size_t)s * RANK;
#pragma unroll 8
    for (int r = 0; r < RANK; r += 4) {
        float4 c4 = *(const float4*)(Cp + r);
        ull cu0 = pack2(c4.x, c4.x);
        ull cu1 = pack2(c4.y, c4.y);
        ull cu2 = pack2(c4.z, c4.z);
        ull cu3 = pack2(c4.w, c4.w);
#pragma unroll
        for (int i = 0; i < 4; i++) {
            int bb = bg * 8 + 2 * i;
            ffma2(acc[i], *(const ull*)&hsh[r + 0][bb], cu0);
            ffma2(acc[i], *(const ull*)&hsh[r + 1][bb], cu1);
            ffma2(acc[i], *(const ull*)&hsh[r + 2][bb], cu2);
            ffma2(acc[i], *(const ull*)&hsh[r + 3][bb], cu3);
        }
    }

    const float bs = beta[s];
#pragma unroll
    for (int i = 0; i < 4; i++) {
        float v0, v1;
        unpack2(acc[i], v0, v1);
        int b = bg * 8 + 2 * i;
        out[(size_t)b       * SDIM + s] = v0 + bs;
        out[(size_t)(b + 1) * SDIM + s] = v1 + bs;
    }
}

// ---------------------------------------------------------------------------
// Launch
// inputs: x[2097152], U[33554432], C[8388608], beta[65536], gamma[1], bn_bias[1]
// ---------------------------------------------------------------------------
extern "C" void kernel_launch(void* const* d_in, const int* in_sizes, int n_in,
                              void* d_out, int out_size) {
    const float* x     = (const float*)d_in[0];
    const float* U     = (const float*)d_in[1];
    const float* C     = (const float*)d_in[2];
    const float* beta  = (const float*)d_in[3];
    const float* gamma = (const float*)d_in[4];
    const float* bnb   = (const float*)d_in[5];
    float* out = (float*)d_out;

    bn_partial_kernel<<<512, 256>>>(x);
    bn_finalize_kernel<<<1, 512>>>(gamma, bnb);
    poly_t_kernel<<<dim3(NCHUNK, NDEG), 128>>>(x, U);
    reduce_partial_kernel<<<512, 256>>>();
    finalize_h_kernel<<<16, 256>>>();
    out_kernel<<<SDIM / TILE_S4, 256>>>(C, beta, out);
}